// round 8
// baseline (speedup 1.0000x reference)
#include <cuda_runtime.h>

#define NNODES 100000
#define NEDGES 3200000
#define DIN 64
#define HID 16

// ---------------- device scratch (no allocations allowed) -------------------
__device__ __align__(256) float g_p1[NNODES * HID];     // x@W1x + b_msg1
__device__ __align__(256) float g_s1[NNODES * HID];     // x@W_skip1 + b_skip1
__device__ __align__(256) float g_acc1[NNODES * 32];    // [0:16) sum p1[src], [16:32) sum ea
__device__ __align__(256) float g_p2[NNODES * HID];     // h@W2x + b_msg2
__device__ __align__(256) float g_s2[NNODES * HID];     // h@W_skip2 + b_skip2
__device__ __align__(256) float g_acc2[NNODES * HID];   // sum p2[src]

__device__ __forceinline__ void red_v4(float* addr, float4 v) {
    asm volatile("red.global.add.v4.f32 [%0], {%1,%2,%3,%4};"
                 :: "l"(addr), "f"(v.x), "f"(v.y), "f"(v.z), "f"(v.w)
                 : "memory");
}

// ---------------------------------------------------------------------------
// K0a: zero g_acc1 (12.8 MB)
// ---------------------------------------------------------------------------
__global__ __launch_bounds__(256) void k_zero1() {
    int i = blockIdx.x * blockDim.x + threadIdx.x;
    if (i < NNODES * 8) reinterpret_cast<float4*>(g_acc1)[i] = make_float4(0.f, 0.f, 0.f, 0.f);
}

// ---------------------------------------------------------------------------
// K0b: zero g_acc2 (6.4 MB)
// ---------------------------------------------------------------------------
__global__ __launch_bounds__(256) void k_zero2() {
    int i = blockIdx.x * blockDim.x + threadIdx.x;
    if (i < NNODES * 4) reinterpret_cast<float4*>(g_acc2)[i] = make_float4(0.f, 0.f, 0.f, 0.f);
}

// ---------------------------------------------------------------------------
// K1: per-node p1 = x@W1x + b_msg1 ; s1 = x@W_skip1 + b_skip1
// ---------------------------------------------------------------------------
__global__ __launch_bounds__(256) void k_node1(
    const float* __restrict__ x,
    const float* __restrict__ Wm1, const float* __restrict__ bm1,
    const float* __restrict__ Ws1, const float* __restrict__ bs1)
{
    __shared__ float sWx[DIN * HID];
    __shared__ float sWs[DIN * HID];
    __shared__ float sx[16][DIN];
    int t = threadIdx.x;
    for (int i = t; i < DIN * HID; i += 256) { sWx[i] = Wm1[i]; sWs[i] = Ws1[i]; }
    int ln = t >> 4, j = t & 15;
    int v = blockIdx.x * 16 + ln;
    if (v < NNODES) {
        reinterpret_cast<float4*>(sx[ln])[j] =
            reinterpret_cast<const float4*>(x + (size_t)v * DIN)[j];
    }
    __syncthreads();
    if (v >= NNODES) return;
    float ap = bm1[j], as = bs1[j];
    #pragma unroll
    for (int k = 0; k < DIN; k++) {
        float xv = sx[ln][k];
        ap = fmaf(xv, sWx[k * HID + j], ap);
        as = fmaf(xv, sWs[k * HID + j], as);
    }
    g_p1[(size_t)v * HID + j] = ap;
    g_s1[(size_t)v * HID + j] = as;
}

// ---------------------------------------------------------------------------
// K2: edge pass 1 — ONE EDGE PER THREAD (MLP=8 on the payload loads)
//   acc1[dst][0:16)  += p1[src]
//   acc1[dst][16:32) += edge_attr[e]
// ---------------------------------------------------------------------------
__global__ __launch_bounds__(256) void k_edge1(
    const int* __restrict__ src, const int* __restrict__ dst,
    const float* __restrict__ ea)
{
    int e = blockIdx.x * blockDim.x + threadIdx.x;
    if (e >= NEDGES) return;
    int s = __ldg(src + e);
    int d = __ldg(dst + e);
    const float4* pe = reinterpret_cast<const float4*>(ea) + (size_t)e * 4;
    const float4* pp = reinterpret_cast<const float4*>(g_p1) + (size_t)s * 4;
    // 8 independent loads in flight
    float4 e0 = __ldg(pe + 0), e1 = __ldg(pe + 1), e2 = __ldg(pe + 2), e3 = __ldg(pe + 3);
    float4 p0 = __ldg(pp + 0), p1v = __ldg(pp + 1), p2v = __ldg(pp + 2), p3 = __ldg(pp + 3);
    float* base = g_acc1 + (size_t)d * 32;
    red_v4(base + 0,  p0);
    red_v4(base + 4,  p1v);
    red_v4(base + 8,  p2v);
    red_v4(base + 12, p3);
    red_v4(base + 16, e0);
    red_v4(base + 20, e1);
    red_v4(base + 24, e2);
    red_v4(base + 28, e3);
}

// ---------------------------------------------------------------------------
// K3: per-node conv1 epilogue + conv2 prologue (one thread per node)
// ---------------------------------------------------------------------------
__global__ __launch_bounds__(256) void k_node2(
    const float* __restrict__ Wm1,
    const float* __restrict__ Wm2, const float* __restrict__ bm2,
    const float* __restrict__ Ws2, const float* __restrict__ bs2)
{
    __shared__ float sWe1[HID * HID];  // W_msg1 rows 64..79
    __shared__ float sW2x[HID * HID];  // W_msg2 rows 0..15
    __shared__ float sWs2[HID * HID];  // W_skip2
    __shared__ float sb2[HID], sbs2[HID];
    int t = threadIdx.x;
    if (t < 256) { sWe1[t] = Wm1[DIN * HID + t]; sW2x[t] = Wm2[t]; sWs2[t] = Ws2[t]; }
    if (t < HID) { sb2[t] = bm2[t]; sbs2[t] = bs2[t]; }
    __syncthreads();
    int v = blockIdx.x * blockDim.x + t;
    if (v >= NNODES) return;

    float accp[16], acce[16], s1v[16];
    const float4* r = reinterpret_cast<const float4*>(g_acc1 + (size_t)v * 32);
    #pragma unroll
    for (int q = 0; q < 4; q++) {
        float4 a = r[q], b = r[q + 4];
        accp[q*4+0]=a.x; accp[q*4+1]=a.y; accp[q*4+2]=a.z; accp[q*4+3]=a.w;
        acce[q*4+0]=b.x; acce[q*4+1]=b.y; acce[q*4+2]=b.z; acce[q*4+3]=b.w;
    }
    const float4* rs = reinterpret_cast<const float4*>(g_s1 + (size_t)v * HID);
    #pragma unroll
    for (int q = 0; q < 4; q++) {
        float4 a = rs[q];
        s1v[q*4+0]=a.x; s1v[q*4+1]=a.y; s1v[q*4+2]=a.z; s1v[q*4+3]=a.w;
    }

    float h[16];
    #pragma unroll
    for (int j = 0; j < HID; j++) {
        float hv = accp[j] + s1v[j];
        #pragma unroll
        for (int k = 0; k < HID; k++) hv = fmaf(acce[k], sWe1[k * HID + j], hv);
        h[j] = fmaxf(hv, 0.f);
    }
    #pragma unroll
    for (int j = 0; j < HID; j++) {
        float pv = sb2[j], sv = sbs2[j];
        #pragma unroll
        for (int k = 0; k < HID; k++) {
            pv = fmaf(h[k], sW2x[k * HID + j], pv);
            sv = fmaf(h[k], sWs2[k * HID + j], sv);
        }
        g_p2[(size_t)v * HID + j] = pv;
        g_s2[(size_t)v * HID + j] = sv;
    }
}

// ---------------------------------------------------------------------------
// K4: edge pass 2 — ONE EDGE PER THREAD (MLP=4)
//   acc2[dst] += p2[src]
// ---------------------------------------------------------------------------
__global__ __launch_bounds__(256) void k_edge2(
    const int* __restrict__ src, const int* __restrict__ dst)
{
    int e = blockIdx.x * blockDim.x + threadIdx.x;
    if (e >= NEDGES) return;
    int s = __ldg(src + e);
    int d = __ldg(dst + e);
    const float4* pp = reinterpret_cast<const float4*>(g_p2) + (size_t)s * 4;
    float4 p0 = __ldg(pp + 0), p1v = __ldg(pp + 1), p2v = __ldg(pp + 2), p3 = __ldg(pp + 3);
    float* base = g_acc2 + (size_t)d * HID;
    red_v4(base + 0,  p0);
    red_v4(base + 4,  p1v);
    red_v4(base + 8,  p2v);
    red_v4(base + 12, p3);
}

// ---------------------------------------------------------------------------
// K5: final epilogue (16 threads per node)
//   h2 = acc2 + acce@We2 + s2 ; out = h2@W_lin3 + b_lin3
// ---------------------------------------------------------------------------
__global__ __launch_bounds__(256) void k_node3(
    const float* __restrict__ Wm2,
    const float* __restrict__ Wl3, const float* __restrict__ bl3,
    float* __restrict__ out)
{
    __shared__ float sWe2[HID * HID];   // W_msg2 rows 16..31
    __shared__ float sWl[HID * DIN];    // W_lin3 (16x64)
    __shared__ float sbl[DIN];
    __shared__ float sh2[16][HID];
    int t = threadIdx.x;
    for (int i = t; i < HID * DIN; i += 256) sWl[i] = Wl3[i];
    if (t < 256) sWe2[t] = Wm2[HID * HID + t];
    if (t < DIN) sbl[t] = bl3[t];
    __syncthreads();

    int ln = t >> 4, j = t & 15;
    int v = blockIdx.x * 16 + ln;
    float val = 0.f;
    if (v < NNODES) {
        val = g_acc2[(size_t)v * HID + j] + g_s2[(size_t)v * HID + j];
        const float* acce = g_acc1 + (size_t)v * 32 + 16;
        #pragma unroll
        for (int k = 0; k < HID; k++) val = fmaf(acce[k], sWe2[k * HID + j], val);
    }
    sh2[ln][j] = val;
    __syncthreads();
    if (v >= NNODES) return;

    float o0 = sbl[j*4+0], o1 = sbl[j*4+1], o2 = sbl[j*4+2], o3 = sbl[j*4+3];
    #pragma unroll
    for (int k = 0; k < HID; k++) {
        float hk = sh2[ln][k];
        const float* w = sWl + k * DIN + j * 4;
        o0 = fmaf(hk, w[0], o0);
        o1 = fmaf(hk, w[1], o1);
        o2 = fmaf(hk, w[2], o2);
        o3 = fmaf(hk, w[3], o3);
    }
    reinterpret_cast<float4*>(out + (size_t)v * DIN)[j] = make_float4(o0, o1, o2, o3);
}

// ---------------------------------------------------------------------------
extern "C" void kernel_launch(void* const* d_in, const int* in_sizes, int n_in,
                              void* d_out, int out_size)
{
    const float* x   = (const float*)d_in[0];
    const int*   ei  = (const int*)  d_in[1];
    const float* ea  = (const float*)d_in[2];
    const float* Wm1 = (const float*)d_in[3];
    const float* bm1 = (const float*)d_in[4];
    const float* Ws1 = (const float*)d_in[5];
    const float* bs1 = (const float*)d_in[6];
    const float* Wm2 = (const float*)d_in[7];
    const float* bm2 = (const float*)d_in[8];
    const float* Ws2 = (const float*)d_in[9];
    const float* bs2 = (const float*)d_in[10];
    const float* Wl3 = (const float*)d_in[11];
    const float* bl3 = (const float*)d_in[12];
    const int* src = ei;
    const int* dst = ei + NEDGES;
    float* out = (float*)d_out;

    // Order: profiled 4th launch = k_edge1 (the dominant kernel).
    k_zero1<<<(NNODES * 8 + 255) / 256, 256>>>();
    k_node1<<<(NNODES + 15) / 16,       256>>>(x, Wm1, bm1, Ws1, bs1);
    k_zero2<<<(NNODES * 4 + 255) / 256, 256>>>();
    k_edge1<<<(NEDGES + 255) / 256,     256>>>(src, dst, ea);
    k_node2<<<(NNODES + 255) / 256,     256>>>(Wm1, Wm2, bm2, Ws2, bs2);
    k_edge2<<<(NEDGES + 255) / 256,     256>>>(src, dst);
    k_node3<<<(NNODES + 15) / 16,       256>>>(Wm2, Wl3, bl3, out);
}

// round 9
// speedup vs baseline: 1.2193x; 1.2193x over previous
#include <cuda_runtime.h>

#define NNODES 100000
#define NEDGES 3200000
#define DIN 64
#define HID 16
#define SCAN_BLK 1024
#define SCAN_CHUNK 4096
#define NSCANBLK 25   // ceil(NNODES / SCAN_CHUNK)

// ---------------- device scratch (no allocations allowed) -------------------
__device__ __align__(256) float g_p1[NNODES * HID];     // x@W1x + b_msg1
__device__ __align__(256) float g_s1[NNODES * HID];     // x@W_skip1 + b_skip1
__device__ __align__(256) float g_p2[NNODES * HID];     // h@W2x + b_msg2
__device__ __align__(256) float g_s2[NNODES * HID];     // h@W_skip2 + b_skip2
__device__ __align__(256) float g_acce[NNODES * HID];   // per-node sum of edge_attr (scatter)
__device__ __align__(256) unsigned g_deg[NNODES];
__device__ __align__(256) unsigned g_off[NNODES + 1];
__device__ __align__(256) unsigned g_cur[NNODES];
__device__ __align__(256) unsigned g_srcs[NEDGES];      // src ids sorted by dst (CSR)
__device__ unsigned g_chain[NSCANBLK];                   // lookback: bit31=flag, low=incl sum

__device__ __forceinline__ void red_v4(float* addr, float4 v) {
    asm volatile("red.global.add.v4.f32 [%0], {%1,%2,%3,%4};"
                 :: "l"(addr), "f"(v.x), "f"(v.y), "f"(v.z), "f"(v.w)
                 : "memory");
}

// ---------------------------------------------------------------------------
// K1: zero g_acce (6.4 MB) + g_deg + g_chain
// ---------------------------------------------------------------------------
__global__ __launch_bounds__(256) void k_zero() {
    int i = blockIdx.x * blockDim.x + threadIdx.x;
    const int nacc = NNODES * 4;                       // g_acce as float4
    if (i < nacc) reinterpret_cast<float4*>(g_acce)[i] = make_float4(0.f, 0.f, 0.f, 0.f);
    else if (i < nacc + NNODES) g_deg[i - nacc] = 0u;
    else if (i < nacc + NNODES + NSCANBLK) g_chain[i - nacc - NNODES] = 0u;
}

// ---------------------------------------------------------------------------
// K2: histogram of dst (4 edges/thread, exact grid)
// ---------------------------------------------------------------------------
__global__ __launch_bounds__(256) void k_hist(const int* __restrict__ dst) {
    int i = blockIdx.x * blockDim.x + threadIdx.x;     // i < NEDGES/4 exactly
    int4 d = __ldg(reinterpret_cast<const int4*>(dst) + i);
    atomicAdd(&g_deg[d.x], 1u);
    atomicAdd(&g_deg[d.y], 1u);
    atomicAdd(&g_deg[d.z], 1u);
    atomicAdd(&g_deg[d.w], 1u);
}

// ---------------------------------------------------------------------------
// K3: SINGLE-KERNEL exclusive scan of g_deg -> g_off,g_cur
//     (block-local scan + 25-block chained lookback; all blocks co-resident)
// ---------------------------------------------------------------------------
__global__ __launch_bounds__(SCAN_BLK) void k_scanA() {
    __shared__ unsigned swarp[32];
    __shared__ unsigned sbase;
    int t = threadIdx.x, b = blockIdx.x;
    int base_i = b * SCAN_CHUNK + t * 4;
    unsigned v[4];
    #pragma unroll
    for (int i = 0; i < 4; i++) v[i] = (base_i + i < NNODES) ? g_deg[base_i + i] : 0u;
    unsigned s = v[0] + v[1] + v[2] + v[3];
    unsigned lane = t & 31, wid = t >> 5;
    unsigned inc = s;
    #pragma unroll
    for (int o = 1; o < 32; o <<= 1) {
        unsigned n = __shfl_up_sync(~0u, inc, o);
        if (lane >= o) inc += n;
    }
    if (lane == 31) swarp[wid] = inc;
    __syncthreads();
    if (wid == 0) {
        unsigned wv = swarp[lane];
        #pragma unroll
        for (int o = 1; o < 32; o <<= 1) {
            unsigned n = __shfl_up_sync(~0u, wv, o);
            if (lane >= o) wv += n;
        }
        swarp[lane] = wv;
    }
    __syncthreads();
    unsigned S = swarp[31];                            // block total
    unsigned run0 = inc - s + (wid ? swarp[wid - 1] : 0u);

    if (t == 0) {
        unsigned base = 0;
        if (b > 0) {
            unsigned val;
            do {
                val = *reinterpret_cast<volatile unsigned*>(&g_chain[b - 1]);
                if (!(val & 0x80000000u)) __nanosleep(40);
            } while (!(val & 0x80000000u));
            base = val & 0x7FFFFFFFu;
        }
        *reinterpret_cast<volatile unsigned*>(&g_chain[b]) = 0x80000000u | (base + S);
        sbase = base;
        if (b == NSCANBLK - 1) g_off[NNODES] = base + S;  // == NEDGES
    }
    __syncthreads();
    unsigned run = run0 + sbase;
    #pragma unroll
    for (int i = 0; i < 4; i++) {
        if (base_i + i < NNODES) { g_off[base_i + i] = run; g_cur[base_i + i] = run; }
        run += v[i];
    }
}

// ---------------------------------------------------------------------------
// K4 (PROFILED SLOT): scatter src into dst-sorted CSR slots, 4 edges/thread
// ---------------------------------------------------------------------------
__global__ __launch_bounds__(256) void k_scatter(const int* __restrict__ src,
                                                 const int* __restrict__ dst) {
    int i = blockIdx.x * blockDim.x + threadIdx.x;     // i < NEDGES/4 exactly
    int4 d4 = __ldg(reinterpret_cast<const int4*>(dst) + i);
    int4 s4 = __ldg(reinterpret_cast<const int4*>(src) + i);
    unsigned q0 = atomicAdd(&g_cur[d4.x], 1u);
    unsigned q1 = atomicAdd(&g_cur[d4.y], 1u);
    unsigned q2 = atomicAdd(&g_cur[d4.z], 1u);
    unsigned q3 = atomicAdd(&g_cur[d4.w], 1u);
    g_srcs[q0] = (unsigned)s4.x;
    g_srcs[q1] = (unsigned)s4.y;
    g_srcs[q2] = (unsigned)s4.z;
    g_srcs[q3] = (unsigned)s4.w;
}

// ---------------------------------------------------------------------------
// K5: per-node p1 = x@W1x + b_msg1 ; s1 = x@W_skip1 + b_skip1
// ---------------------------------------------------------------------------
__global__ __launch_bounds__(256) void k_node1(
    const float* __restrict__ x,
    const float* __restrict__ Wm1, const float* __restrict__ bm1,
    const float* __restrict__ Ws1, const float* __restrict__ bs1)
{
    __shared__ float sWx[DIN * HID];
    __shared__ float sWs[DIN * HID];
    __shared__ float sx[16][DIN];
    int t = threadIdx.x;
    for (int i = t; i < DIN * HID; i += 256) { sWx[i] = Wm1[i]; sWs[i] = Ws1[i]; }
    int ln = t >> 4, j = t & 15;
    int v = blockIdx.x * 16 + ln;
    if (v < NNODES) {
        reinterpret_cast<float4*>(sx[ln])[j] =
            reinterpret_cast<const float4*>(x + (size_t)v * DIN)[j];
    }
    __syncthreads();
    if (v >= NNODES) return;
    float ap = bm1[j], as = bs1[j];
    #pragma unroll
    for (int k = 0; k < DIN; k++) {
        float xv = sx[ln][k];
        ap = fmaf(xv, sWx[k * HID + j], ap);
        as = fmaf(xv, sWs[k * HID + j], as);
    }
    g_p1[(size_t)v * HID + j] = ap;
    g_s1[(size_t)v * HID + j] = as;
}

// ---------------------------------------------------------------------------
// K6: streaming ea scatter — acc_e[dst] += edge_attr[e] (4 lanes/edge,
//     coalesced RED layout — MEASURED 51us, RED-throughput bound)
// ---------------------------------------------------------------------------
__global__ __launch_bounds__(256) void k_edge_ea(const int* __restrict__ dst,
                                                 const float* __restrict__ ea) {
    int tid = blockIdx.x * blockDim.x + threadIdx.x;
    if (tid >= NEDGES * 4) return;
    int i = tid >> 2, c = tid & 3;
    float4 e = reinterpret_cast<const float4*>(ea)[tid];   // coalesced stream
    int d = __ldg(dst + i);
    red_v4(g_acce + (size_t)d * HID + c * 4, e);
}

// ---------------------------------------------------------------------------
// Batched CSR gather (MLP=4 on both index and row loads)
// ---------------------------------------------------------------------------
__device__ __forceinline__ float4 gather_sum(const float* __restrict__ tbl,
                                             unsigned beg, unsigned end,
                                             int slot, int c)
{
    float4 a0 = make_float4(0.f, 0.f, 0.f, 0.f);
    float4 a1 = a0, a2 = a0, a3 = a0;
    unsigned idx = beg + slot;
    for (; idx + 24 < end; idx += 32) {
        unsigned s0 = __ldg(g_srcs + idx);
        unsigned s1 = __ldg(g_srcs + idx + 8);
        unsigned s2 = __ldg(g_srcs + idx + 16);
        unsigned s3 = __ldg(g_srcs + idx + 24);
        float4 q0 = __ldg(reinterpret_cast<const float4*>(tbl + (size_t)s0 * HID) + c);
        float4 q1 = __ldg(reinterpret_cast<const float4*>(tbl + (size_t)s1 * HID) + c);
        float4 q2 = __ldg(reinterpret_cast<const float4*>(tbl + (size_t)s2 * HID) + c);
        float4 q3 = __ldg(reinterpret_cast<const float4*>(tbl + (size_t)s3 * HID) + c);
        a0.x += q0.x; a0.y += q0.y; a0.z += q0.z; a0.w += q0.w;
        a1.x += q1.x; a1.y += q1.y; a1.z += q1.z; a1.w += q1.w;
        a2.x += q2.x; a2.y += q2.y; a2.z += q2.z; a2.w += q2.w;
        a3.x += q3.x; a3.y += q3.y; a3.z += q3.z; a3.w += q3.w;
    }
    for (; idx < end; idx += 8) {
        unsigned s = __ldg(g_srcs + idx);
        float4 q = __ldg(reinterpret_cast<const float4*>(tbl + (size_t)s * HID) + c);
        a0.x += q.x; a0.y += q.y; a0.z += q.z; a0.w += q.w;
    }
    a0.x += a1.x + a2.x + a3.x;
    a0.y += a1.y + a2.y + a3.y;
    a0.z += a1.z + a2.z + a3.z;
    a0.w += a1.w + a2.w + a3.w;
    return a0;
}

// ---------------------------------------------------------------------------
// K7: conv1 gather-aggregate + fused node math
// ---------------------------------------------------------------------------
__global__ __launch_bounds__(256) void k_agg1(
    const float* __restrict__ Wm1,
    const float* __restrict__ Wm2, const float* __restrict__ bm2,
    const float* __restrict__ Ws2, const float* __restrict__ bs2)
{
    __shared__ float sWe1[HID * HID], sW2x[HID * HID], sWs2[HID * HID];
    __shared__ float sb2[HID], sbs2[HID];
    __shared__ float sacc[8][HID];
    __shared__ float sae[8][HID];
    __shared__ float sh[8][HID];
    int t = threadIdx.x;
    if (t < 256) { sWe1[t] = Wm1[DIN * HID + t]; sW2x[t] = Wm2[t]; sWs2[t] = Ws2[t]; }
    if (t < HID) { sb2[t] = bm2[t]; sbs2[t] = bs2[t]; }

    int w = t >> 5, lane = t & 31;
    int v = blockIdx.x * 8 + w;            // grid = NNODES/8 exactly
    int slot = lane >> 2, c = lane & 3;
    unsigned beg = g_off[v], end = g_off[v + 1];
    if (lane < HID) sae[w][lane] = g_acce[(size_t)v * HID + lane];

    float4 ap = gather_sum(g_p1, beg, end, slot, c);
    #pragma unroll
    for (int m = 4; m <= 16; m <<= 1) {
        ap.x += __shfl_xor_sync(~0u, ap.x, m);
        ap.y += __shfl_xor_sync(~0u, ap.y, m);
        ap.z += __shfl_xor_sync(~0u, ap.z, m);
        ap.w += __shfl_xor_sync(~0u, ap.w, m);
    }
    if (lane < 4) reinterpret_cast<float4*>(sacc[w])[lane] = ap;
    __syncthreads();

    int ln = t >> 4, j = t & 15;
    if (t < 128) {
        int v2 = blockIdx.x * 8 + ln;
        float hv = sacc[ln][j] + g_s1[(size_t)v2 * HID + j];
        #pragma unroll
        for (int k = 0; k < HID; k++) hv = fmaf(sae[ln][k], sWe1[k * HID + j], hv);
        sh[ln][j] = fmaxf(hv, 0.f);
    }
    __syncthreads();
    if (t < 128) {
        int v2 = blockIdx.x * 8 + ln;
        float pv = sb2[j], sv = sbs2[j];
        #pragma unroll
        for (int k = 0; k < HID; k++) {
            float hk = sh[ln][k];
            pv = fmaf(hk, sW2x[k * HID + j], pv);
            sv = fmaf(hk, sWs2[k * HID + j], sv);
        }
        g_p2[(size_t)v2 * HID + j] = pv;
        g_s2[(size_t)v2 * HID + j] = sv;
    }
}

// ---------------------------------------------------------------------------
// K8: conv2 gather-aggregate + fused final projection
// ---------------------------------------------------------------------------
__global__ __launch_bounds__(256) void k_agg2(
    const float* __restrict__ Wm2,
    const float* __restrict__ Wl3, const float* __restrict__ bl3,
    float* __restrict__ out)
{
    __shared__ float sWe2[HID * HID];
    __shared__ float sWl[HID * DIN];
    __shared__ float sbl[DIN];
    __shared__ float sacc[8][HID];
    __shared__ float sae[8][HID];
    __shared__ float sh2[8][HID];
    int t = threadIdx.x;
    if (t < 256) sWe2[t] = Wm2[HID * HID + t];
    for (int i = t; i < HID * DIN; i += 256) sWl[i] = Wl3[i];
    if (t < DIN) sbl[t] = bl3[t];

    int w = t >> 5, lane = t & 31;
    int v = blockIdx.x * 8 + w;
    int slot = lane >> 2, c = lane & 3;
    unsigned beg = g_off[v], end = g_off[v + 1];
    if (lane < HID) sae[w][lane] = g_acce[(size_t)v * HID + lane];

    float4 ap = gather_sum(g_p2, beg, end, slot, c);
    #pragma unroll
    for (int m = 4; m <= 16; m <<= 1) {
        ap.x += __shfl_xor_sync(~0u, ap.x, m);
        ap.y += __shfl_xor_sync(~0u, ap.y, m);
        ap.z += __shfl_xor_sync(~0u, ap.z, m);
        ap.w += __shfl_xor_sync(~0u, ap.w, m);
    }
    if (lane < 4) reinterpret_cast<float4*>(sacc[w])[lane] = ap;
    __syncthreads();

    int ln = t >> 4, j = t & 15;
    if (t < 128) {
        int v2 = blockIdx.x * 8 + ln;
        float hv = sacc[ln][j] + g_s2[(size_t)v2 * HID + j];
        #pragma unroll
        for (int k = 0; k < HID; k++) hv = fmaf(sae[ln][k], sWe2[k * HID + j], hv);
        sh2[ln][j] = hv;
    }
    __syncthreads();

    // 8 nodes x 64 outputs = 512 per block, 2 per thread
    #pragma unroll
    for (int r = 0; r < 2; r++) {
        int o = t + r * 256;
        int ln2 = o >> 6, col = o & 63;
        int v3 = blockIdx.x * 8 + ln2;
        float acc = sbl[col];
        #pragma unroll
        for (int k = 0; k < HID; k++) acc = fmaf(sh2[ln2][k], sWl[k * DIN + col], acc);
        out[(size_t)v3 * DIN + col] = acc;
    }
}

// ---------------------------------------------------------------------------
extern "C" void kernel_launch(void* const* d_in, const int* in_sizes, int n_in,
                              void* d_out, int out_size)
{
    const float* x   = (const float*)d_in[0];
    const int*   ei  = (const int*)  d_in[1];
    const float* ea  = (const float*)d_in[2];
    const float* Wm1 = (const float*)d_in[3];
    const float* bm1 = (const float*)d_in[4];
    const float* Ws1 = (const float*)d_in[5];
    const float* bs1 = (const float*)d_in[6];
    const float* Wm2 = (const float*)d_in[7];
    const float* bm2 = (const float*)d_in[8];
    const float* Ws2 = (const float*)d_in[9];
    const float* bs2 = (const float*)d_in[10];
    const float* Wl3 = (const float*)d_in[11];
    const float* bl3 = (const float*)d_in[12];
    const int* src = ei;
    const int* dst = ei + NEDGES;
    float* out = (float*)d_out;

    // Launch order: 4th = k_scatter (the decisive profile measurement).
    k_zero   <<<(NNODES * 5 + NSCANBLK + 255) / 256, 256>>>();
    k_hist   <<<NEDGES / 4 / 256, 256>>>(dst);
    k_scanA  <<<NSCANBLK, SCAN_BLK>>>();
    k_scatter<<<NEDGES / 4 / 256, 256>>>(src, dst);
    k_node1  <<<(NNODES + 15) / 16, 256>>>(x, Wm1, bm1, Ws1, bs1);
    k_edge_ea<<<(NEDGES * 4 + 255) / 256, 256>>>(dst, ea);
    k_agg1   <<<NNODES / 8, 256>>>(Wm1, Wm2, bm2, Ws2, bs2);
    k_agg2   <<<NNODES / 8, 256>>>(Wm2, Wl3, bl3, out);
}

// round 10
// speedup vs baseline: 1.2423x; 1.0189x over previous
#include <cuda_runtime.h>

#define NNODES 100000
#define NEDGES 3200000
#define DIN 64
#define HID 16
#define SCAN_BLK 1024
#define SCAN_CHUNK 4096
#define NSCANBLK 25   // ceil(NNODES / SCAN_CHUNK)

// ---------------- device scratch (no allocations allowed) -------------------
__device__ __align__(256) float g_p1[NNODES * HID];     // x@W1x + b_msg1
__device__ __align__(256) float g_s1[NNODES * HID];     // x@W_skip1 + b_skip1
__device__ __align__(256) float g_p2[NNODES * HID];     // h@W2x + b_msg2
__device__ __align__(256) float g_s2[NNODES * HID];     // h@W_skip2 + b_skip2
__device__ __align__(256) float g_acce[NNODES * HID];   // per-node sum of edge_attr (scatter)
__device__ __align__(256) unsigned g_deg[NNODES];
__device__ __align__(256) unsigned g_off[NNODES + 1];
__device__ __align__(256) unsigned g_cur[NNODES];
__device__ __align__(256) unsigned g_srcs[NEDGES];      // src ids sorted by dst (CSR)
__device__ unsigned g_chain[NSCANBLK];                   // lookback: bit31=flag, low=incl sum

__device__ __forceinline__ void red_v4(float* addr, float4 v) {
    asm volatile("red.global.add.v4.f32 [%0], {%1,%2,%3,%4};"
                 :: "l"(addr), "f"(v.x), "f"(v.y), "f"(v.z), "f"(v.w)
                 : "memory");
}

// ---------------------------------------------------------------------------
// K1: zero g_acce (6.4 MB) + g_deg + g_chain
// ---------------------------------------------------------------------------
__global__ __launch_bounds__(256) void k_zero() {
    int i = blockIdx.x * blockDim.x + threadIdx.x;
    const int nacc = NNODES * 4;                       // g_acce as float4
    if (i < nacc) reinterpret_cast<float4*>(g_acce)[i] = make_float4(0.f, 0.f, 0.f, 0.f);
    else if (i < nacc + NNODES) g_deg[i - nacc] = 0u;
    else if (i < nacc + NNODES + NSCANBLK) g_chain[i - nacc - NNODES] = 0u;
}

// ---------------------------------------------------------------------------
// K2: histogram of dst (4 edges/thread, exact grid)
// ---------------------------------------------------------------------------
__global__ __launch_bounds__(256) void k_hist(const int* __restrict__ dst) {
    int i = blockIdx.x * blockDim.x + threadIdx.x;     // i < NEDGES/4 exactly
    int4 d = __ldg(reinterpret_cast<const int4*>(dst) + i);
    atomicAdd(&g_deg[d.x], 1u);
    atomicAdd(&g_deg[d.y], 1u);
    atomicAdd(&g_deg[d.z], 1u);
    atomicAdd(&g_deg[d.w], 1u);
}

// ---------------------------------------------------------------------------
// K3: per-node p1 = x@W1x + b_msg1 ; s1 = x@W_skip1 + b_skip1
// ---------------------------------------------------------------------------
__global__ __launch_bounds__(256) void k_node1(
    const float* __restrict__ x,
    const float* __restrict__ Wm1, const float* __restrict__ bm1,
    const float* __restrict__ Ws1, const float* __restrict__ bs1)
{
    __shared__ float sWx[DIN * HID];
    __shared__ float sWs[DIN * HID];
    __shared__ float sx[16][DIN];
    int t = threadIdx.x;
    for (int i = t; i < DIN * HID; i += 256) { sWx[i] = Wm1[i]; sWs[i] = Ws1[i]; }
    int ln = t >> 4, j = t & 15;
    int v = blockIdx.x * 16 + ln;
    if (v < NNODES) {
        reinterpret_cast<float4*>(sx[ln])[j] =
            reinterpret_cast<const float4*>(x + (size_t)v * DIN)[j];
    }
    __syncthreads();
    if (v >= NNODES) return;
    float ap = bm1[j], as = bs1[j];
    #pragma unroll
    for (int k = 0; k < DIN; k++) {
        float xv = sx[ln][k];
        ap = fmaf(xv, sWx[k * HID + j], ap);
        as = fmaf(xv, sWs[k * HID + j], as);
    }
    g_p1[(size_t)v * HID + j] = ap;
    g_s1[(size_t)v * HID + j] = as;
}

// ---------------------------------------------------------------------------
// K4 (PROFILED SLOT, control): streaming ea scatter — measured ~51us
// ---------------------------------------------------------------------------
__global__ __launch_bounds__(256) void k_edge_ea(const int* __restrict__ dst,
                                                 const float* __restrict__ ea) {
    int tid = blockIdx.x * blockDim.x + threadIdx.x;
    if (tid >= NEDGES * 4) return;
    int i = tid >> 2, c = tid & 3;
    float4 e = reinterpret_cast<const float4*>(ea)[tid];   // coalesced stream
    int d = __ldg(dst + i);
    red_v4(g_acce + (size_t)d * HID + c * 4, e);
}

// ---------------------------------------------------------------------------
// K5: SINGLE-KERNEL exclusive scan of g_deg -> g_off,g_cur (chained lookback)
// ---------------------------------------------------------------------------
__global__ __launch_bounds__(SCAN_BLK) void k_scanA() {
    __shared__ unsigned swarp[32];
    __shared__ unsigned sbase;
    int t = threadIdx.x, b = blockIdx.x;
    int base_i = b * SCAN_CHUNK + t * 4;
    unsigned v[4];
    #pragma unroll
    for (int i = 0; i < 4; i++) v[i] = (base_i + i < NNODES) ? g_deg[base_i + i] : 0u;
    unsigned s = v[0] + v[1] + v[2] + v[3];
    unsigned lane = t & 31, wid = t >> 5;
    unsigned inc = s;
    #pragma unroll
    for (int o = 1; o < 32; o <<= 1) {
        unsigned n = __shfl_up_sync(~0u, inc, o);
        if (lane >= o) inc += n;
    }
    if (lane == 31) swarp[wid] = inc;
    __syncthreads();
    if (wid == 0) {
        unsigned wv = swarp[lane];
        #pragma unroll
        for (int o = 1; o < 32; o <<= 1) {
            unsigned n = __shfl_up_sync(~0u, wv, o);
            if (lane >= o) wv += n;
        }
        swarp[lane] = wv;
    }
    __syncthreads();
    unsigned S = swarp[31];                            // block total
    unsigned run0 = inc - s + (wid ? swarp[wid - 1] : 0u);

    if (t == 0) {
        unsigned base = 0;
        if (b > 0) {
            unsigned val;
            do {
                val = *reinterpret_cast<volatile unsigned*>(&g_chain[b - 1]);
                if (!(val & 0x80000000u)) __nanosleep(40);
            } while (!(val & 0x80000000u));
            base = val & 0x7FFFFFFFu;
        }
        *reinterpret_cast<volatile unsigned*>(&g_chain[b]) = 0x80000000u | (base + S);
        sbase = base;
        if (b == NSCANBLK - 1) g_off[NNODES] = base + S;  // == NEDGES
    }
    __syncthreads();
    unsigned run = run0 + sbase;
    #pragma unroll
    for (int i = 0; i < 4; i++) {
        if (base_i + i < NNODES) { g_off[base_i + i] = run; g_cur[base_i + i] = run; }
        run += v[i];
    }
}

// ---------------------------------------------------------------------------
// K6: scatter src into dst-sorted CSR slots, 4 edges/thread (measured 45us)
// ---------------------------------------------------------------------------
__global__ __launch_bounds__(256) void k_scatter(const int* __restrict__ src,
                                                 const int* __restrict__ dst) {
    int i = blockIdx.x * blockDim.x + threadIdx.x;     // i < NEDGES/4 exactly
    int4 d4 = __ldg(reinterpret_cast<const int4*>(dst) + i);
    int4 s4 = __ldg(reinterpret_cast<const int4*>(src) + i);
    unsigned q0 = atomicAdd(&g_cur[d4.x], 1u);
    unsigned q1 = atomicAdd(&g_cur[d4.y], 1u);
    unsigned q2 = atomicAdd(&g_cur[d4.z], 1u);
    unsigned q3 = atomicAdd(&g_cur[d4.w], 1u);
    g_srcs[q0] = (unsigned)s4.x;
    g_srcs[q1] = (unsigned)s4.y;
    g_srcs[q2] = (unsigned)s4.z;
    g_srcs[q3] = (unsigned)s4.w;
}

// ---------------------------------------------------------------------------
// Edge-parallel gather: warp loads 32 indices coalesced, shuffle-broadcasts
// them to 8 chunk-groups; 4 independent row gathers in flight per lane.
// lane = g*4 + c : group g in [0,8), chunk c in [0,4).
// ---------------------------------------------------------------------------
__device__ __forceinline__ float4 gather_sum(const float* __restrict__ tbl,
                                             unsigned beg, unsigned end,
                                             int g, int c, int lane)
{
    float4 acc = make_float4(0.f, 0.f, 0.f, 0.f);
    for (unsigned base = beg; base < end; base += 32) {
        unsigned myi = base + (unsigned)lane;
        unsigned sidx = (myi < end) ? __ldg(g_srcs + myi) : 0xFFFFFFFFu;
        float4 q[4];
        #pragma unroll
        for (int r = 0; r < 4; r++) {
            unsigned e = __shfl_sync(0xFFFFFFFFu, sidx, g + r * 8);
            if (e != 0xFFFFFFFFu)
                q[r] = __ldg(reinterpret_cast<const float4*>(tbl + (size_t)e * HID) + c);
            else
                q[r] = make_float4(0.f, 0.f, 0.f, 0.f);
        }
        acc.x += (q[0].x + q[1].x) + (q[2].x + q[3].x);
        acc.y += (q[0].y + q[1].y) + (q[2].y + q[3].y);
        acc.z += (q[0].z + q[1].z) + (q[2].z + q[3].z);
        acc.w += (q[0].w + q[1].w) + (q[2].w + q[3].w);
    }
    return acc;
}

// ---------------------------------------------------------------------------
// K7: conv1 gather-aggregate + fused node math
// ---------------------------------------------------------------------------
__global__ __launch_bounds__(256) void k_agg1(
    const float* __restrict__ Wm1,
    const float* __restrict__ Wm2, const float* __restrict__ bm2,
    const float* __restrict__ Ws2, const float* __restrict__ bs2)
{
    __shared__ float sWe1[HID * HID], sW2x[HID * HID], sWs2[HID * HID];
    __shared__ float sb2[HID], sbs2[HID];
    __shared__ float sacc[8][HID];
    __shared__ float sae[8][HID];
    __shared__ float sh[8][HID];
    int t = threadIdx.x;
    if (t < 256) { sWe1[t] = Wm1[DIN * HID + t]; sW2x[t] = Wm2[t]; sWs2[t] = Ws2[t]; }
    if (t < HID) { sb2[t] = bm2[t]; sbs2[t] = bs2[t]; }

    int w = t >> 5, lane = t & 31;
    int v = blockIdx.x * 8 + w;            // grid = NNODES/8 exactly
    int g = lane >> 2, c = lane & 3;
    unsigned beg = g_off[v], end = g_off[v + 1];
    if (lane < HID) sae[w][lane] = g_acce[(size_t)v * HID + lane];

    float4 ap = gather_sum(g_p1, beg, end, g, c, lane);
    #pragma unroll
    for (int m = 4; m <= 16; m <<= 1) {
        ap.x += __shfl_xor_sync(~0u, ap.x, m);
        ap.y += __shfl_xor_sync(~0u, ap.y, m);
        ap.z += __shfl_xor_sync(~0u, ap.z, m);
        ap.w += __shfl_xor_sync(~0u, ap.w, m);
    }
    if (lane < 4) reinterpret_cast<float4*>(sacc[w])[lane] = ap;
    __syncthreads();

    int ln = t >> 4, j = t & 15;
    if (t < 128) {
        int v2 = blockIdx.x * 8 + ln;
        float hv = sacc[ln][j] + g_s1[(size_t)v2 * HID + j];
        #pragma unroll
        for (int k = 0; k < HID; k++) hv = fmaf(sae[ln][k], sWe1[k * HID + j], hv);
        sh[ln][j] = fmaxf(hv, 0.f);
    }
    __syncthreads();
    if (t < 128) {
        int v2 = blockIdx.x * 8 + ln;
        float pv = sb2[j], sv = sbs2[j];
        #pragma unroll
        for (int k = 0; k < HID; k++) {
            float hk = sh[ln][k];
            pv = fmaf(hk, sW2x[k * HID + j], pv);
            sv = fmaf(hk, sWs2[k * HID + j], sv);
        }
        g_p2[(size_t)v2 * HID + j] = pv;
        g_s2[(size_t)v2 * HID + j] = sv;
    }
}

// ---------------------------------------------------------------------------
// K8: conv2 gather-aggregate + fused final projection
// ---------------------------------------------------------------------------
__global__ __launch_bounds__(256) void k_agg2(
    const float* __restrict__ Wm2,
    const float* __restrict__ Wl3, const float* __restrict__ bl3,
    float* __restrict__ out)
{
    __shared__ float sWe2[HID * HID];
    __shared__ float sWl[HID * DIN];
    __shared__ float sbl[DIN];
    __shared__ float sacc[8][HID];
    __shared__ float sae[8][HID];
    __shared__ float sh2[8][HID];
    int t = threadIdx.x;
    if (t < 256) sWe2[t] = Wm2[HID * HID + t];
    for (int i = t; i < HID * DIN; i += 256) sWl[i] = Wl3[i];
    if (t < DIN) sbl[t] = bl3[t];

    int w = t >> 5, lane = t & 31;
    int v = blockIdx.x * 8 + w;
    int g = lane >> 2, c = lane & 3;
    unsigned beg = g_off[v], end = g_off[v + 1];
    if (lane < HID) sae[w][lane] = g_acce[(size_t)v * HID + lane];

    float4 ap = gather_sum(g_p2, beg, end, g, c, lane);
    #pragma unroll
    for (int m = 4; m <= 16; m <<= 1) {
        ap.x += __shfl_xor_sync(~0u, ap.x, m);
        ap.y += __shfl_xor_sync(~0u, ap.y, m);
        ap.z += __shfl_xor_sync(~0u, ap.z, m);
        ap.w += __shfl_xor_sync(~0u, ap.w, m);
    }
    if (lane < 4) reinterpret_cast<float4*>(sacc[w])[lane] = ap;
    __syncthreads();

    int ln = t >> 4, j = t & 15;
    if (t < 128) {
        int v2 = blockIdx.x * 8 + ln;
        float hv = sacc[ln][j] + g_s2[(size_t)v2 * HID + j];
        #pragma unroll
        for (int k = 0; k < HID; k++) hv = fmaf(sae[ln][k], sWe2[k * HID + j], hv);
        sh2[ln][j] = hv;
    }
    __syncthreads();

    // 8 nodes x 64 outputs = 512 per block, 2 per thread
    #pragma unroll
    for (int r = 0; r < 2; r++) {
        int o = t + r * 256;
        int ln2 = o >> 6, col = o & 63;
        int v3 = blockIdx.x * 8 + ln2;
        float acc = sbl[col];
        #pragma unroll
        for (int k = 0; k < HID; k++) acc = fmaf(sh2[ln2][k], sWl[k * DIN + col], acc);
        out[(size_t)v3 * DIN + col] = acc;
    }
}

// ---------------------------------------------------------------------------
extern "C" void kernel_launch(void* const* d_in, const int* in_sizes, int n_in,
                              void* d_out, int out_size)
{
    const float* x   = (const float*)d_in[0];
    const int*   ei  = (const int*)  d_in[1];
    const float* ea  = (const float*)d_in[2];
    const float* Wm1 = (const float*)d_in[3];
    const float* bm1 = (const float*)d_in[4];
    const float* Ws1 = (const float*)d_in[5];
    const float* bs1 = (const float*)d_in[6];
    const float* Wm2 = (const float*)d_in[7];
    const float* bm2 = (const float*)d_in[8];
    const float* Ws2 = (const float*)d_in[9];
    const float* bs2 = (const float*)d_in[10];
    const float* Wl3 = (const float*)d_in[11];
    const float* bl3 = (const float*)d_in[12];
    const int* src = ei;
    const int* dst = ei + NEDGES;
    float* out = (float*)d_out;

    // Launch order: 4th = k_edge_ea (known control measurement).
    k_zero   <<<(NNODES * 5 + NSCANBLK + 255) / 256, 256>>>();
    k_hist   <<<NEDGES / 4 / 256, 256>>>(dst);
    k_node1  <<<(NNODES + 15) / 16, 256>>>(x, Wm1, bm1, Ws1, bs1);
    k_edge_ea<<<(NEDGES * 4 + 255) / 256, 256>>>(dst, ea);
    k_scanA  <<<NSCANBLK, SCAN_BLK>>>();
    k_scatter<<<NEDGES / 4 / 256, 256>>>(src, dst);
    k_agg1   <<<NNODES / 8, 256>>>(Wm1, Wm2, bm2, Ws2, bs2);
    k_agg2   <<<NNODES / 8, 256>>>(Wm2, Wl3, bl3, out);
}